// round 6
// baseline (speedup 1.0000x reference)
#include <cuda_runtime.h>
#include <cuda_fp16.h>
#include <cstdint>

#define NUM_T 2048
#define NUM_H 1024
#define NUM_I 1024
#define NUM_E 8
#define NROWS (NUM_T * 2)

#define BM 128
#define BN 256
#define BK 32
#define KTILES 32          // 1024 / BK
#define STAGES 4
#define A_STRIDE 40        // halves; 80B rows  -> conflict-free LDSM
#define B_STRIDE 264       // halves; 528B rows -> conflict-free LDSM.trans (132w % 32 = 4)
#define A_BYTES (BM * A_STRIDE * 2)          // 10240
#define B_BYTES (BK * B_STRIDE * 2)          // 16896
#define STAGE_BYTES (A_BYTES + B_BYTES)      // 27136
#define SMEM_GEMM (STAGES * STAGE_BYTES)     // 108544 (>= 128*132*4 = 67584 epilogue)

// ---------------- device scratch (static: no allocations allowed) ----------------
__device__ int    d_count[NUM_E];
__device__ int    d_offset[NUM_E + 1];
__device__ float  d_topk_w[NROWS];
__device__ int    d_tok_row[NROWS];      // token -> its 2 rows
__device__ int    d_row_token[NROWS];    // row -> token

__device__ __half d_w13h[(size_t)NUM_E * 1024 * 2048];   // interleaved cols, 32MB
__device__ __half d_w2h [(size_t)NUM_E * 1024 * 1024];   // 16MB
__device__ __half d_x16 [(size_t)NUM_T * 1024];          // 4MB
__device__ __half d_inter[(size_t)NROWS * 1024];         // 8MB
__device__ float  d_y   [(size_t)NROWS * 1024];          // 16MB (gemm2 per-row out)

// ---------------- ptx helpers ----------------
__device__ __forceinline__ uint32_t smem_u32(const void* p) {
    uint32_t a;
    asm("{ .reg .u64 t; cvta.to.shared.u64 t, %1; cvt.u32.u64 %0, t; }" : "=r"(a) : "l"(p));
    return a;
}
__device__ __forceinline__ void cpa16(uint32_t dst, const void* src, uint32_t srcbytes) {
    asm volatile("cp.async.cg.shared.global [%0], [%1], 16, %2;"
                 :: "r"(dst), "l"(src), "r"(srcbytes));
}
__device__ __forceinline__ void cpa_commit() { asm volatile("cp.async.commit_group;" ::: "memory"); }
__device__ __forceinline__ void ldsm_x4(uint32_t* r, uint32_t addr) {
    asm volatile("ldmatrix.sync.aligned.m8n8.x4.shared.b16 {%0,%1,%2,%3}, [%4];"
                 : "=r"(r[0]), "=r"(r[1]), "=r"(r[2]), "=r"(r[3]) : "r"(addr));
}
__device__ __forceinline__ void ldsm_x4t(uint32_t* r, uint32_t addr) {
    asm volatile("ldmatrix.sync.aligned.m8n8.x4.trans.shared.b16 {%0,%1,%2,%3}, [%4];"
                 : "=r"(r[0]), "=r"(r[1]), "=r"(r[2]), "=r"(r[3]) : "r"(addr));
}
__device__ __forceinline__ void hmma(float* c, const uint32_t* a, const uint32_t* b) {
    asm volatile(
        "mma.sync.aligned.m16n8k16.row.col.f32.f16.f16.f32 "
        "{%0,%1,%2,%3}, {%4,%5,%6,%7}, {%8,%9}, {%0,%1,%2,%3};"
        : "+f"(c[0]), "+f"(c[1]), "+f"(c[2]), "+f"(c[3])
        : "r"(a[0]), "r"(a[1]), "r"(a[2]), "r"(a[3]), "r"(b[0]), "r"(b[1]));
}

__device__ __forceinline__ uint2 pack4(float4 v) {
    __half2 p0 = __halves2half2(__float2half_rn(v.x), __float2half_rn(v.y));
    __half2 p1 = __halves2half2(__float2half_rn(v.z), __float2half_rn(v.w));
    uint2 h;
    h.x = *reinterpret_cast<uint32_t*>(&p0);
    h.y = *reinterpret_cast<uint32_t*>(&p1);
    return h;
}
__device__ __forceinline__ uint32_t pack2(float a, float b) {
    __half2 p = __halves2half2(__float2half_rn(a), __float2half_rn(b));
    return *reinterpret_cast<uint32_t*>(&p);
}

// ---------------- prep: fp32 -> fp16 (w13 column-interleaved, 128-granular) ----------------
__global__ void prep_kernel(const float* __restrict__ x, const float* __restrict__ w13,
                            const float* __restrict__ w2) {
    const int stride = gridDim.x * blockDim.x;
    const int tid = blockIdx.x * blockDim.x + threadIdx.x;
    // w13 interleave: gate col c -> (c>>7)*256 + (c&127); up col c -> (c>>7)*256 + 128 + (c&127)
    for (int i = tid; i < (NUM_E * 1024 * 2048) / 4; i += stride) {
        float4 v = reinterpret_cast<const float4*>(w13)[i];
        int f = i * 4;
        int c = f & 2047;
        size_t rowbase = (size_t)(f >> 11) * 2048;
        int dc = (c < 1024) ? ((c >> 7) * 256 + (c & 127))
                            : (((c - 1024) >> 7) * 256 + 128 + ((c - 1024) & 127));
        *reinterpret_cast<uint2*>(d_w13h + rowbase + dc) = pack4(v);
    }
    for (int i = tid; i < (NUM_E * 1024 * 1024) / 4; i += stride) {
        float4 v = reinterpret_cast<const float4*>(w2)[i];
        reinterpret_cast<uint2*>(d_w2h)[i] = pack4(v);
    }
    for (int i = tid; i < (NUM_T * 1024) / 4; i += stride) {
        float4 v = reinterpret_cast<const float4*>(x)[i];
        reinterpret_cast<uint2*>(d_x16)[i] = pack4(v);
    }
}

// ---------------- routing: single block does top2 + scan + assign ----------------
__global__ void route_all(const float* __restrict__ logits) {
    __shared__ int cnt[NUM_E], off[NUM_E], cur[NUM_E];
    const int tx = threadIdx.x;   // 1024 threads, 2 tokens each
    if (tx < NUM_E) { cnt[tx] = 0; cur[tx] = 0; }
    __syncthreads();
    int ids[2][2];
#pragma unroll
    for (int u = 0; u < 2; u++) {
        int t = tx + u * 1024;
        float l[NUM_E];
#pragma unroll
        for (int e = 0; e < NUM_E; e++) l[e] = logits[t * NUM_E + e];
        int i0 = 0; float v0 = l[0];
#pragma unroll
        for (int e = 1; e < NUM_E; e++) if (l[e] > v0) { v0 = l[e]; i0 = e; }
        int i1 = -1; float v1 = -1e30f;
#pragma unroll
        for (int e = 0; e < NUM_E; e++) if (e != i0 && l[e] > v1) { v1 = l[e]; i1 = e; }
        float z  = expf(v1 - v0);
        float w0 = 1.0f / (1.0f + z);
        d_topk_w[t * 2] = w0;
        d_topk_w[t * 2 + 1] = 1.0f - w0;
        ids[u][0] = i0; ids[u][1] = i1;
        atomicAdd(&cnt[i0], 1);
        atomicAdd(&cnt[i1], 1);
    }
    __syncthreads();
    if (tx == 0) {
        int s = 0;
#pragma unroll
        for (int e = 0; e < NUM_E; e++) {
            off[e] = s; d_offset[e] = s; d_count[e] = cnt[e]; s += cnt[e];
        }
        d_offset[NUM_E] = s;
    }
    __syncthreads();
#pragma unroll
    for (int u = 0; u < 2; u++) {
        int t = tx + u * 1024;
#pragma unroll
        for (int k = 0; k < 2; k++) {
            int e = ids[u][k];
            int pos = atomicAdd(&cur[e], 1);
            int row = off[e] + pos;
            d_row_token[row] = t;
            d_tok_row[t * 2 + k] = row;
        }
    }
}

// ---------------- grouped GEMM: 128x256 CTA tile, 8 warps of 64x64 ----------------
// G2=false: acc = x16[token(row)] @ w13h[e] (interleaved); epilogue: silu(g)*u -> d_inter fp16
// G2=true : acc = d_inter[row] @ w2h[e];                   epilogue: d_y[row] = acc
template <bool G2, int NGLOB>
__global__ void __launch_bounds__(256) gemm_cl() {
    extern __shared__ __align__(128) char smem[];
    const uint32_t sb = smem_u32(smem);
    const int tid = threadIdx.x, wid = tid >> 5, lane = tid & 31;

    const int e   = blockIdx.y >> 4;
    const int mt  = blockIdx.y & 15;
    const int cnt = d_count[e];
    const int m0  = mt * BM;
    if (m0 >= cnt) return;
    const int off  = d_offset[e];
    const int n0   = blockIdx.x * BN;
    const int row0 = off + m0;

    const __half* Bw = (G2 ? d_w2h : d_w13h) + (size_t)e * 1024 * NGLOB;

    // A loader: 2 iterations, rows (tid>>2) and +64, 16B segment (tid&3)
    const int r0a = tid >> 2;
    const int s0  = tid & 3;
    const bool v0 = (m0 + r0a) < cnt;
    const bool v1 = (m0 + r0a + 64) < cnt;
    const __half *Arow0, *Arow1;
    if (G2) {
        int g0 = min(row0 + r0a, NROWS - 1);
        int g1 = min(row0 + r0a + 64, NROWS - 1);
        Arow0 = d_inter + (size_t)g0 * 1024;
        Arow1 = d_inter + (size_t)g1 * 1024;
    } else {
        int g0 = v0 ? d_row_token[row0 + r0a] : 0;
        int g1 = v1 ? d_row_token[row0 + r0a + 64] : 0;
        Arow0 = d_x16 + (size_t)g0 * 1024;
        Arow1 = d_x16 + (size_t)g1 * 1024;
    }
    // B loader: 4 iterations; q = tid + 256*it: row q>>5 (0..31), seg q&31 (32 x 16B per row)
    const int br0 = tid >> 5;       // +8 per iteration
    const int bs0 = tid & 31;

    auto load_stage = [&](int stg, int k0) {
        uint32_t base = sb + (uint32_t)stg * STAGE_BYTES;
        uint32_t da = base + (uint32_t)(r0a * 80 + s0 * 16);
        cpa16(da,            Arow0 + k0 + s0 * 8, v0 ? 16u : 0u);
        cpa16(da + 64 * 80,  Arow1 + k0 + s0 * 8, v1 ? 16u : 0u);
        uint32_t db = base + A_BYTES + (uint32_t)(br0 * 528 + bs0 * 16);
        const __half* bsrc = Bw + (size_t)(k0 + br0) * NGLOB + n0 + bs0 * 8;
#pragma unroll
        for (int it = 0; it < 4; it++)
            cpa16(db + it * 8 * 528, bsrc + (size_t)it * 8 * NGLOB, 16u);
    };

    const int warpM = (wid >> 2) * 64;
    const int warpN = (wid & 3) * 64;

    float acc[4][8][4];
#pragma unroll
    for (int i = 0; i < 4; i++)
#pragma unroll
        for (int j = 0; j < 8; j++)
#pragma unroll
            for (int q = 0; q < 4; q++) acc[i][j][q] = 0.f;

    const int a_row = lane & 15;
    const int a_col = (lane >> 4) << 3;
    const int b_row = (lane & 7) + (((lane >> 3) & 1) << 3);
    const int b_col = (lane >> 4) << 3;

#pragma unroll
    for (int s = 0; s < STAGES - 1; s++) { load_stage(s, s * BK); cpa_commit(); }

    for (int kt = 0; kt < KTILES; kt++) {
        asm volatile("cp.async.wait_group %0;" :: "n"(STAGES - 2));
        __syncthreads();
        int nk = kt + STAGES - 1;
        if (nk < KTILES) load_stage(nk & (STAGES - 1), nk * BK);
        cpa_commit();

        uint32_t As = sb + (uint32_t)(kt & (STAGES - 1)) * STAGE_BYTES;
        uint32_t Bs = As + A_BYTES;
#pragma unroll
        for (int kk = 0; kk < BK; kk += 16) {
            uint32_t af[4][4], bt[4][4];
#pragma unroll
            for (int i = 0; i < 4; i++)
                ldsm_x4(af[i], As + (uint32_t)((warpM + i * 16 + a_row) * 80 + (kk + a_col) * 2));
#pragma unroll
            for (int j2 = 0; j2 < 4; j2++)
                ldsm_x4t(bt[j2], Bs + (uint32_t)((kk + b_row) * 528 + (warpN + j2 * 16 + b_col) * 2));
#pragma unroll
            for (int i = 0; i < 4; i++)
#pragma unroll
                for (int j = 0; j < 8; j++)
                    hmma(acc[i][j], af[i], &bt[j >> 1][(j & 1) * 2]);
        }
    }

    // ---------------- epilogue ----------------
    const int gq = lane >> 2, tg = lane & 3;
    if (!G2) {
        // gate warps (warpN < 128) stage gate fp32 to smem; up warps fuse silu*u -> fp16
        asm volatile("cp.async.wait_group 0;" ::: "memory");
        __syncthreads();
        float* S = reinterpret_cast<float*>(smem);   // [128][132]
        const int half_n = wid & 3;   // 0,1 gate; 2,3 up
        if (half_n < 2) {
#pragma unroll
            for (int i = 0; i < 4; i++) {
                int rlo = warpM + i * 16 + gq;
#pragma unroll
                for (int j = 0; j < 8; j++) {
                    int c = half_n * 64 + j * 8 + 2 * tg;
                    *reinterpret_cast<float2*>(&S[rlo * 132 + c]) =
                        make_float2(acc[i][j][0], acc[i][j][1]);
                    *reinterpret_cast<float2*>(&S[(rlo + 8) * 132 + c]) =
                        make_float2(acc[i][j][2], acc[i][j][3]);
                }
            }
        }
        __syncthreads();
        if (half_n >= 2) {
            const int icol0 = blockIdx.x * 128;
#pragma unroll
            for (int i = 0; i < 4; i++) {
                int rlo = warpM + i * 16 + gq;
                int rhi = rlo + 8;
                bool wlo = (m0 + rlo) < cnt;
                bool whi = (m0 + rhi) < cnt;
#pragma unroll
                for (int j = 0; j < 8; j++) {
                    int c = (half_n - 2) * 64 + j * 8 + 2 * tg;
                    if (wlo) {
                        float g0 = S[rlo * 132 + c], g1 = S[rlo * 132 + c + 1];
                        float o0 = g0 / (1.f + expf(-g0)) * acc[i][j][0];
                        float o1 = g1 / (1.f + expf(-g1)) * acc[i][j][1];
                        *reinterpret_cast<uint32_t*>(
                            d_inter + (size_t)(row0 + rlo) * 1024 + icol0 + c) = pack2(o0, o1);
                    }
                    if (whi) {
                        float g2 = S[rhi * 132 + c], g3 = S[rhi * 132 + c + 1];
                        float o2 = g2 / (1.f + expf(-g2)) * acc[i][j][2];
                        float o3 = g3 / (1.f + expf(-g3)) * acc[i][j][3];
                        *reinterpret_cast<uint32_t*>(
                            d_inter + (size_t)(row0 + rhi) * 1024 + icol0 + c) = pack2(o2, o3);
                    }
                }
            }
        }
    } else {
#pragma unroll
        for (int i = 0; i < 4; i++) {
            int mlo = warpM + i * 16 + gq;
            int mhi = mlo + 8;
            bool wlo = (m0 + mlo) < cnt;
            bool whi = (m0 + mhi) < cnt;
#pragma unroll
            for (int j = 0; j < 8; j++) {
                int c = n0 + warpN + j * 8 + 2 * tg;
                if (wlo)
                    *reinterpret_cast<float2*>(d_y + (size_t)(row0 + mlo) * 1024 + c) =
                        make_float2(acc[i][j][0], acc[i][j][1]);
                if (whi)
                    *reinterpret_cast<float2*>(d_y + (size_t)(row0 + mhi) * 1024 + c) =
                        make_float2(acc[i][j][2], acc[i][j][3]);
            }
        }
    }
}

// ---------------- finalize: out[t] = w0*y[r0] + w1*y[r1] ----------------
__global__ void finalize_kernel(float* __restrict__ out) {
    int t = blockIdx.x;
    int c = threadIdx.x * 4;
    int r0 = d_tok_row[t * 2], r1 = d_tok_row[t * 2 + 1];
    float w0 = d_topk_w[t * 2], w1 = d_topk_w[t * 2 + 1];
    float4 a = *reinterpret_cast<const float4*>(d_y + (size_t)r0 * 1024 + c);
    float4 b = *reinterpret_cast<const float4*>(d_y + (size_t)r1 * 1024 + c);
    float4 o;
    o.x = w0 * a.x + w1 * b.x;
    o.y = w0 * a.y + w1 * b.y;
    o.z = w0 * a.z + w1 * b.z;
    o.w = w0 * a.w + w1 * b.w;
    *reinterpret_cast<float4*>(out + (size_t)t * NUM_H + c) = o;
}

// ---------------- launch ----------------
extern "C" void kernel_launch(void* const* d_in, const int* in_sizes, int n_in,
                              void* d_out, int out_size) {
    const float* x      = (const float*)d_in[0];
    const float* logits = (const float*)d_in[1];
    const float* w13    = (const float*)d_in[2];
    const float* w2     = (const float*)d_in[3];
    float* out = (float*)d_out;

    cudaFuncSetAttribute(gemm_cl<false, 2048>, cudaFuncAttributeMaxDynamicSharedMemorySize, SMEM_GEMM);
    cudaFuncSetAttribute(gemm_cl<true, 1024>,  cudaFuncAttributeMaxDynamicSharedMemorySize, SMEM_GEMM);

    prep_kernel<<<1024, 256>>>(x, w13, w2);
    route_all<<<1, 1024>>>(logits);
    gemm_cl<false, 2048><<<dim3(2048 / BN, NUM_E * 16), 256, SMEM_GEMM>>>();
    gemm_cl<true, 1024><<<dim3(1024 / BN, NUM_E * 16), 256, SMEM_GEMM>>>();
    finalize_kernel<<<NUM_T, 256>>>(out);
}

// round 7
// speedup vs baseline: 1.2203x; 1.2203x over previous
#include <cuda_runtime.h>
#include <cuda_fp16.h>
#include <cstdint>

#define NUM_T 2048
#define NUM_H 1024
#define NUM_I 1024
#define NUM_E 8
#define NROWS (NUM_T * 2)

#define BM 128
#define BN 128
#define BK 64
#define KTILES 16          // 1024 / BK
#define STAGES 3
#define A_STRIDE 72        // halves; 144B rows -> conflict-free LDSM (18r mod 32 distinct)
#define B_STRIDE 136       // halves; 272B rows -> conflict-free LDSM.trans
#define A_BYTES (BM * A_STRIDE * 2)          // 18432
#define B_BYTES (BK * B_STRIDE * 2)          // 17408
#define STAGE_BYTES (A_BYTES + B_BYTES)      // 35840
#define SMEM_GEMM (STAGES * STAGE_BYTES)     // 107520 (>= 128*132*4 = 67584 epilogue)

// ---------------- device scratch (static: no allocations allowed) ----------------
__device__ int    d_count[NUM_E];
__device__ int    d_offset[NUM_E + 1];
__device__ float  d_topk_w[NROWS];
__device__ int    d_tok_row[NROWS];      // token -> its 2 rows
__device__ int    d_row_token[NROWS];    // row -> token

__device__ __half d_w13h[(size_t)NUM_E * 1024 * 2048];   // interleaved cols, 32MB
__device__ __half d_w2h [(size_t)NUM_E * 1024 * 1024];   // 16MB
__device__ __half d_x16 [(size_t)NUM_T * 1024];          // 4MB
__device__ __half d_inter[(size_t)NROWS * 1024];         // 8MB
__device__ float  d_y   [(size_t)NROWS * 1024];          // 16MB (gemm2 per-row out)

// ---------------- ptx helpers ----------------
__device__ __forceinline__ uint32_t smem_u32(const void* p) {
    uint32_t a;
    asm("{ .reg .u64 t; cvta.to.shared.u64 t, %1; cvt.u32.u64 %0, t; }" : "=r"(a) : "l"(p));
    return a;
}
__device__ __forceinline__ void cpa16(uint32_t dst, const void* src, uint32_t srcbytes) {
    asm volatile("cp.async.cg.shared.global [%0], [%1], 16, %2;"
                 :: "r"(dst), "l"(src), "r"(srcbytes));
}
__device__ __forceinline__ void cpa_commit() { asm volatile("cp.async.commit_group;" ::: "memory"); }
__device__ __forceinline__ void ldsm_x4(uint32_t* r, uint32_t addr) {
    asm volatile("ldmatrix.sync.aligned.m8n8.x4.shared.b16 {%0,%1,%2,%3}, [%4];"
                 : "=r"(r[0]), "=r"(r[1]), "=r"(r[2]), "=r"(r[3]) : "r"(addr));
}
__device__ __forceinline__ void ldsm_x4t(uint32_t* r, uint32_t addr) {
    asm volatile("ldmatrix.sync.aligned.m8n8.x4.trans.shared.b16 {%0,%1,%2,%3}, [%4];"
                 : "=r"(r[0]), "=r"(r[1]), "=r"(r[2]), "=r"(r[3]) : "r"(addr));
}
__device__ __forceinline__ void hmma(float* c, const uint32_t* a, const uint32_t* b) {
    asm volatile(
        "mma.sync.aligned.m16n8k16.row.col.f32.f16.f16.f32 "
        "{%0,%1,%2,%3}, {%4,%5,%6,%7}, {%8,%9}, {%0,%1,%2,%3};"
        : "+f"(c[0]), "+f"(c[1]), "+f"(c[2]), "+f"(c[3])
        : "r"(a[0]), "r"(a[1]), "r"(a[2]), "r"(a[3]), "r"(b[0]), "r"(b[1]));
}

__device__ __forceinline__ uint2 pack4(float4 v) {
    __half2 p0 = __halves2half2(__float2half_rn(v.x), __float2half_rn(v.y));
    __half2 p1 = __halves2half2(__float2half_rn(v.z), __float2half_rn(v.w));
    uint2 h;
    h.x = *reinterpret_cast<uint32_t*>(&p0);
    h.y = *reinterpret_cast<uint32_t*>(&p1);
    return h;
}

// ---------------- prep: routing (block 0) + fp32 -> fp16 converts (blocks 1..) ----------------
__global__ void prep_kernel(const float* __restrict__ x, const float* __restrict__ logits,
                            const float* __restrict__ w13, const float* __restrict__ w2) {
    if (blockIdx.x == 0) {
        // ---- routing: top2 + scan + assign, 256 threads, 8 tokens each ----
        __shared__ int cnt[NUM_E], off[NUM_E], cur[NUM_E];
        const int tx = threadIdx.x;
        if (tx < NUM_E) { cnt[tx] = 0; cur[tx] = 0; }
        __syncthreads();
        int ids[8][2];
#pragma unroll
        for (int u = 0; u < 8; u++) {
            int t = tx + u * 256;
            float l[NUM_E];
#pragma unroll
            for (int e = 0; e < NUM_E; e++) l[e] = logits[t * NUM_E + e];
            int i0 = 0; float v0 = l[0];
#pragma unroll
            for (int e = 1; e < NUM_E; e++) if (l[e] > v0) { v0 = l[e]; i0 = e; }
            int i1 = -1; float v1 = -1e30f;
#pragma unroll
            for (int e = 0; e < NUM_E; e++) if (e != i0 && l[e] > v1) { v1 = l[e]; i1 = e; }
            float z  = expf(v1 - v0);
            float w0 = 1.0f / (1.0f + z);
            d_topk_w[t * 2] = w0;
            d_topk_w[t * 2 + 1] = 1.0f - w0;
            ids[u][0] = i0; ids[u][1] = i1;
            atomicAdd(&cnt[i0], 1);
            atomicAdd(&cnt[i1], 1);
        }
        __syncthreads();
        if (tx == 0) {
            int s = 0;
#pragma unroll
            for (int e = 0; e < NUM_E; e++) {
                off[e] = s; d_offset[e] = s; d_count[e] = cnt[e]; s += cnt[e];
            }
            d_offset[NUM_E] = s;
        }
        __syncthreads();
#pragma unroll
        for (int u = 0; u < 8; u++) {
            int t = tx + u * 256;
#pragma unroll
            for (int k = 0; k < 2; k++) {
                int e = ids[u][k];
                int pos = atomicAdd(&cur[e], 1);
                int row = off[e] + pos;
                d_row_token[row] = t;
                d_tok_row[t * 2 + k] = row;
            }
        }
        return;
    }
    // ---- conversions (blocks 1..gridDim-1) ----
    const int stride = (gridDim.x - 1) * blockDim.x;
    const int tid = (blockIdx.x - 1) * blockDim.x + threadIdx.x;
    // w13 interleave: gate col c -> (c>>6)*128 + (c&63); up col c -> (c>>6)*128 + 64 + (c&63)
    for (int i = tid; i < (NUM_E * 1024 * 2048) / 4; i += stride) {
        float4 v = reinterpret_cast<const float4*>(w13)[i];
        int f = i * 4;
        int c = f & 2047;
        size_t rowbase = (size_t)(f >> 11) * 2048;
        int dc = (c < 1024) ? ((c >> 6) * 128 + (c & 63))
                            : (((c - 1024) >> 6) * 128 + 64 + ((c - 1024) & 63));
        *reinterpret_cast<uint2*>(d_w13h + rowbase + dc) = pack4(v);
    }
    for (int i = tid; i < (NUM_E * 1024 * 1024) / 4; i += stride) {
        float4 v = reinterpret_cast<const float4*>(w2)[i];
        reinterpret_cast<uint2*>(d_w2h)[i] = pack4(v);
    }
    for (int i = tid; i < (NUM_T * 1024) / 4; i += stride) {
        float4 v = reinterpret_cast<const float4*>(x)[i];
        reinterpret_cast<uint2*>(d_x16)[i] = pack4(v);
    }
}

// ---------------- grouped GEMM: 128x128 CTA tile, 8 warps 64x32, BK=64, 3 stages ----------------
// G2=false: acc = x16[token(row)] @ w13h[e] (interleaved); epilogue: silu(g)*u -> d_inter fp16
// G2=true : acc = d_inter[row] @ w2h[e];                   epilogue: d_y[row] = acc
template <bool G2, int NGLOB>
__global__ void __launch_bounds__(256, 2) gemm_cl() {
    extern __shared__ __align__(128) char smem[];
    const uint32_t sb = smem_u32(smem);
    const int tid = threadIdx.x, wid = tid >> 5, lane = tid & 31;

    const int e   = blockIdx.y >> 4;
    const int mt  = blockIdx.y & 15;
    const int cnt = d_count[e];
    const int m0  = mt * BM;
    if (m0 >= cnt) return;
    const int off  = d_offset[e];
    const int n0   = blockIdx.x * BN;
    const int row0 = off + m0;

    const __half* Bw = (G2 ? d_w2h : d_w13h) + (size_t)e * 1024 * NGLOB;

    // A loader: rows (tid>>2, +64), 16B segs (tid&3) and (tid&3)+4  -> covers 64 halves
    const int r0a = tid >> 2;
    const int s0  = tid & 3;
    const bool v0 = (m0 + r0a) < cnt;
    const bool v1 = (m0 + r0a + 64) < cnt;
    const __half *Arow0, *Arow1;
    if (G2) {
        int g0 = min(row0 + r0a, NROWS - 1);
        int g1 = min(row0 + r0a + 64, NROWS - 1);
        Arow0 = d_inter + (size_t)g0 * 1024;
        Arow1 = d_inter + (size_t)g1 * 1024;
    } else {
        int g0 = v0 ? d_row_token[row0 + r0a] : 0;
        int g1 = v1 ? d_row_token[row0 + r0a + 64] : 0;
        Arow0 = d_x16 + (size_t)g0 * 1024;
        Arow1 = d_x16 + (size_t)g1 * 1024;
    }
    // B loader: k-rows (tid>>4) + {0,16,32,48}, 16B seg (tid&15)
    const int br0 = tid >> 4;
    const int bs0 = tid & 15;

    auto load_stage = [&](int stg, int k0) {
        uint32_t base = sb + (uint32_t)stg * STAGE_BYTES;
        uint32_t da = base + (uint32_t)(r0a * 144 + s0 * 16);
        cpa16(da,                 Arow0 + k0 + s0 * 8,        v0 ? 16u : 0u);
        cpa16(da + 64,            Arow0 + k0 + (s0 + 4) * 8,  v0 ? 16u : 0u);
        cpa16(da + 64 * 144,      Arow1 + k0 + s0 * 8,        v1 ? 16u : 0u);
        cpa16(da + 64 * 144 + 64, Arow1 + k0 + (s0 + 4) * 8,  v1 ? 16u : 0u);
        uint32_t db = base + A_BYTES + (uint32_t)(br0 * 272 + bs0 * 16);
        const __half* bsrc = Bw + (size_t)(k0 + br0) * NGLOB + n0 + bs0 * 8;
#pragma unroll
        for (int it = 0; it < 4; it++)
            cpa16(db + it * 16 * 272, bsrc + (size_t)it * 16 * NGLOB, 16u);
    };

    const int warpM = (wid >> 2) * 64;
    const int warpN = (wid & 3) * 32;

    float acc[4][4][4];
#pragma unroll
    for (int i = 0; i < 4; i++)
#pragma unroll
        for (int j = 0; j < 4; j++)
#pragma unroll
            for (int q = 0; q < 4; q++) acc[i][j][q] = 0.f;

    const int a_row = lane & 15;
    const int a_col = (lane >> 4) << 3;
    const int b_row = (lane & 7) + (((lane >> 3) & 1) << 3);
    const int b_col = (lane >> 4) << 3;

#pragma unroll
    for (int s = 0; s < STAGES - 1; s++) { load_stage(s, s * BK); cpa_commit(); }

    int stg = 0;
    for (int kt = 0; kt < KTILES; kt++) {
        asm volatile("cp.async.wait_group %0;" :: "n"(STAGES - 2));
        __syncthreads();
        int nk = kt + STAGES - 1;
        if (nk < KTILES) {
            int ns = stg + (STAGES - 1); if (ns >= STAGES) ns -= STAGES;
            load_stage(ns, nk * BK);
        }
        cpa_commit();

        uint32_t As = sb + (uint32_t)stg * STAGE_BYTES;
        uint32_t Bs = As + A_BYTES;
#pragma unroll
        for (int kk = 0; kk < BK; kk += 16) {
            uint32_t af[4][4], bt[2][4];
#pragma unroll
            for (int i = 0; i < 4; i++)
                ldsm_x4(af[i], As + (uint32_t)((warpM + i * 16 + a_row) * 144 + (kk + a_col) * 2));
#pragma unroll
            for (int j2 = 0; j2 < 2; j2++)
                ldsm_x4t(bt[j2], Bs + (uint32_t)((kk + b_row) * 272 + (warpN + j2 * 16 + b_col) * 2));
#pragma unroll
            for (int i = 0; i < 4; i++)
#pragma unroll
                for (int j = 0; j < 4; j++)
                    hmma(acc[i][j], af[i], &bt[j >> 1][(j & 1) * 2]);
        }
        if (++stg == STAGES) stg = 0;
    }

    // ---------------- epilogue ----------------
    const int gq = lane >> 2, tg = lane & 3;
    if (!G2) {
        // stage acc in smem, fuse swiglu, write fp16 inter (cols bx*64 .. +64)
        asm volatile("cp.async.wait_group 0;" ::: "memory");
        __syncthreads();
        float* S = reinterpret_cast<float*>(smem);   // [128][132]
#pragma unroll
        for (int i = 0; i < 4; i++) {
            int rlo = warpM + i * 16 + gq;
#pragma unroll
            for (int j = 0; j < 4; j++) {
                int c = warpN + j * 8 + 2 * tg;
                *reinterpret_cast<float2*>(&S[rlo * 132 + c]) =
                    make_float2(acc[i][j][0], acc[i][j][1]);
                *reinterpret_cast<float2*>(&S[(rlo + 8) * 132 + c]) =
                    make_float2(acc[i][j][2], acc[i][j][3]);
            }
        }
        __syncthreads();
        const int jj = (tid & 15) * 4;
        const int icol = blockIdx.x * 64 + jj;
#pragma unroll
        for (int p = 0; p < 8; p++) {
            int r = (tid >> 4) + p * 16;
            if (m0 + r < cnt) {
                float4 g = *reinterpret_cast<float4*>(&S[r * 132 + jj]);
                float4 u = *reinterpret_cast<float4*>(&S[r * 132 + 64 + jj]);
                float o0 = g.x / (1.f + expf(-g.x)) * u.x;
                float o1 = g.y / (1.f + expf(-g.y)) * u.y;
                float o2 = g.z / (1.f + expf(-g.z)) * u.z;
                float o3 = g.w / (1.f + expf(-g.w)) * u.w;
                *reinterpret_cast<uint2*>(d_inter + (size_t)(row0 + r) * 1024 + icol) =
                    pack4(make_float4(o0, o1, o2, o3));
            }
        }
    } else {
        // plain store of per-row result (weights applied in finalize)
#pragma unroll
        for (int i = 0; i < 4; i++) {
            int mlo = warpM + i * 16 + gq;
            int mhi = mlo + 8;
            bool wlo = (m0 + mlo) < cnt;
            bool whi = (m0 + mhi) < cnt;
#pragma unroll
            for (int j = 0; j < 4; j++) {
                int c = n0 + warpN + j * 8 + 2 * tg;
                if (wlo)
                    *reinterpret_cast<float2*>(d_y + (size_t)(row0 + mlo) * 1024 + c) =
                        make_float2(acc[i][j][0], acc[i][j][1]);
                if (whi)
                    *reinterpret_cast<float2*>(d_y + (size_t)(row0 + mhi) * 1024 + c) =
                        make_float2(acc[i][j][2], acc[i][j][3]);
            }
        }
    }
}

// ---------------- finalize: out[t] = w0*y[r0] + w1*y[r1] ----------------
__global__ void finalize_kernel(float* __restrict__ out) {
    int t = blockIdx.x;
    int c = threadIdx.x * 4;
    int r0 = d_tok_row[t * 2], r1 = d_tok_row[t * 2 + 1];
    float w0 = d_topk_w[t * 2], w1 = d_topk_w[t * 2 + 1];
    float4 a = *reinterpret_cast<const float4*>(d_y + (size_t)r0 * 1024 + c);
    float4 b = *reinterpret_cast<const float4*>(d_y + (size_t)r1 * 1024 + c);
    float4 o;
    o.x = w0 * a.x + w1 * b.x;
    o.y = w0 * a.y + w1 * b.y;
    o.z = w0 * a.z + w1 * b.z;
    o.w = w0 * a.w + w1 * b.w;
    *reinterpret_cast<float4*>(out + (size_t)t * NUM_H + c) = o;
}

// ---------------- launch ----------------
extern "C" void kernel_launch(void* const* d_in, const int* in_sizes, int n_in,
                              void* d_out, int out_size) {
    const float* x      = (const float*)d_in[0];
    const float* logits = (const float*)d_in[1];
    const float* w13    = (const float*)d_in[2];
    const float* w2     = (const float*)d_in[3];
    float* out = (float*)d_out;

    cudaFuncSetAttribute(gemm_cl<false, 2048>, cudaFuncAttributeMaxDynamicSharedMemorySize, SMEM_GEMM);
    cudaFuncSetAttribute(gemm_cl<true, 1024>,  cudaFuncAttributeMaxDynamicSharedMemorySize, SMEM_GEMM);

    prep_kernel<<<1025, 256>>>(x, logits, w13, w2);
    gemm_cl<false, 2048><<<dim3(2048 / BN, NUM_E * 16), 256, SMEM_GEMM>>>();
    gemm_cl<true, 1024><<<dim3(1024 / BN, NUM_E * 16), 256, SMEM_GEMM>>>();
    finalize_kernel<<<NUM_T, 256>>>(out);
}